// round 7
// baseline (speedup 1.0000x reference)
#include <cuda_runtime.h>
#include <cuda_fp16.h>
#include <cstddef>
#include <cstdint>

// Problem constants (fixed by the dataset)
#define NN   50000
#define EE   800000
#define GG   512
#define CH   128
#define CIN  64
#define NEG_SLOPE 0.01f

#define TILE_M 128
#define GEMM_BLOCKS ((NN + TILE_M - 1) / TILE_M)

// ---------------------------------------------------------------------------
// Device-global scratch
// ---------------------------------------------------------------------------
__device__ __half g_h16A[NN * CH];
__device__ __half g_h16B[NN * CH];
__device__ __half g_x16[NN * CIN];
__device__ __half g_W16[12 * 128 * 256];   // [layer][n=128][k=256]
__device__ float g_inv[NN];
__device__ int   g_deg[NN];
__device__ int   g_rowptr[NN + 1];
__device__ int   g_cursor[NN];
__device__ int   g_col[EE];
__device__ float g_pool[GG * CH];
__device__ float g_gcnt[GG];

// ---------------------------------------------------------------------------
// Utility kernels
// ---------------------------------------------------------------------------
__global__ void k_zero_f(float* p, int n) {
    int i = blockIdx.x * blockDim.x + threadIdx.x;
    if (i < n) p[i] = 0.0f;
}
__global__ void k_zero_i(int* p, int n) {
    int i = blockIdx.x * blockDim.x + threadIdx.x;
    if (i < n) p[i] = 0;
}
__global__ void k_count(const int* __restrict__ dst) {
    int i = blockIdx.x * blockDim.x + threadIdx.x;
    if (i < EE) atomicAdd(&g_deg[dst[i]], 1);
}

__global__ void k_scan() {
    __shared__ int sdata[1024];
    __shared__ int s_total;
    const int tid = threadIdx.x;
    if (tid == 0) s_total = 0;
    __syncthreads();
    for (int base = 0; base < NN; base += 1024) {
        int i = base + tid;
        int v = (i < NN) ? g_deg[i] : 0;
        sdata[tid] = v;
        __syncthreads();
        #pragma unroll
        for (int off = 1; off < 1024; off <<= 1) {
            int t = (tid >= off) ? sdata[tid - off] : 0;
            __syncthreads();
            sdata[tid] += t;
            __syncthreads();
        }
        int incl = sdata[tid];
        int excl = incl - v;
        int run = s_total;
        if (i < NN) {
            g_rowptr[i] = run + excl;
            g_cursor[i] = run + excl;
            g_inv[i] = 1.0f / (float)max(v, 1);
        }
        __syncthreads();
        if (tid == 1023) s_total = run + incl;
        __syncthreads();
    }
    if (tid == 0) g_rowptr[NN] = s_total;
}

__global__ void k_fill(const int* __restrict__ src, const int* __restrict__ dst) {
    int i = blockIdx.x * blockDim.x + threadIdx.x;
    if (i < EE) {
        int d = dst[i];
        int pos = atomicAdd(&g_cursor[d], 1);
        g_col[pos] = src[i];
    }
}

// Convert input features x (fp32) -> fp16
__global__ void k_cvt_x(const float* __restrict__ x) {
    int i = blockIdx.x * blockDim.x + threadIdx.x;
    if (i < NN * CIN) g_x16[i] = __float2half_rn(x[i]);
}

// Build transposed fp16 weight table: g_W16[l][n][k] = Wcat_l[k][n]
__global__ void k_w16(const float* __restrict__ Wl0, const float* __restrict__ Wr0,
                      const float* __restrict__ Wl, const float* __restrict__ Wr) {
    int idx = blockIdx.x * blockDim.x + threadIdx.x;
    if (idx >= 12 * 128 * 256) return;
    int l = idx >> 15;
    int n = (idx >> 8) & 127;
    int k = idx & 255;
    float v = 0.0f;
    if (l == 0) {
        if (k < 64)       v = Wl0[k * 128 + n];
        else if (k < 128) v = Wr0[(k - 64) * 128 + n];
    } else {
        int i = l - 1;
        if (k < 128) v = Wl[(size_t)i * 128 * 128 + k * 128 + n];
        else         v = Wr[(size_t)i * 128 * 128 + (k - 128) * 128 + n];
    }
    g_W16[idx] = __float2half_rn(v);
}

// ---------------------------------------------------------------------------
// FUSED SAGEConv layer: gather-mean aggregation straight into the smem A-tile,
// then fp16 m16n8k16 mma over concatenated K = [agg | h].
//   Out[m][n] = [mean_nbr(Hf)[m] | Hf[m]] @ W16_l^T + bias[n], activation.
// BM=128, BN=128, BK=32. 256 threads = 8 warps (4m x 2n), warp tile 32x64.
// smem: A full tile [128][2*KH+8] halves + B stage [128][40] halves.
// ACT: 0=none, 1=relu, 2=leaky
// ---------------------------------------------------------------------------
#define BS_STR 40

template <int KH, int ACT>
__global__ __launch_bounds__(256, 2) void k_fused(
    const __half* __restrict__ Hf,   // [NN][KH] node features
    const __half* __restrict__ W16,  // [128][256] transposed weights (layer slice)
    const float* __restrict__ bias,  // [128]
    __half* __restrict__ Out)        // [NN][128]
{
    constexpr int KT = 2 * KH;
    constexpr int ASTR = KT + 8;
    extern __shared__ __half sm[];
    __half* As = sm;                       // [128][ASTR]
    __half* Bs = sm + 128 * ASTR;          // [128][BS_STR]

    const int tid = threadIdx.x;
    const int wid = tid >> 5;
    const int lane = tid & 31;
    const int wm = wid & 3;
    const int wn2 = wid >> 2;
    const int m0 = blockIdx.x * TILE_M;

    // ---- phase 1a: self features into A[k = KH .. KT) ----
    {
        const int row = tid >> 1;
        const int off = (tid & 1) * (KH / 2);
        const int m = m0 + row;
        if (m < NN) {
            const __half* p = Hf + (size_t)m * KH + off;
            #pragma unroll
            for (int j = 0; j < KH / 16; j++)
                *(uint4*)&As[row * ASTR + KH + off + j * 8] = *(const uint4*)(p + j * 8);
        } else {
            #pragma unroll
            for (int j = 0; j < KH / 16; j++)
                *(uint4*)&As[row * ASTR + KH + off + j * 8] = make_uint4(0, 0, 0, 0);
        }
    }

    // ---- phase 1b: gather-mean into A[k = 0 .. KH), warp per node ----
    #pragma unroll 1
    for (int i = 0; i < 16; i++) {
        const int row = wid * 16 + i;
        const int gw = m0 + row;
        if constexpr (KH == 128) {
            float4 acc = make_float4(0.f, 0.f, 0.f, 0.f);
            if (gw < NN) {
                const int b = g_rowptr[gw], e = g_rowptr[gw + 1];
                const float iv = g_inv[gw];
                const uint2* hp = (const uint2*)Hf;
                for (int j = b; j < e; j++) {
                    int s = g_col[j];
                    uint2 u = hp[s * 32 + lane];
                    float2 a = __half22float2(*(const __half2*)&u.x);
                    float2 c2 = __half22float2(*(const __half2*)&u.y);
                    acc.x += a.x; acc.y += a.y; acc.z += c2.x; acc.w += c2.y;
                }
                acc.x *= iv; acc.y *= iv; acc.z *= iv; acc.w *= iv;
            }
            uint2 o;
            *(__half2*)&o.x = __floats2half2_rn(acc.x, acc.y);
            *(__half2*)&o.y = __floats2half2_rn(acc.z, acc.w);
            *(uint2*)&As[row * ASTR + lane * 4] = o;
        } else {  // KH == 64
            float2 acc = make_float2(0.f, 0.f);
            if (gw < NN) {
                const int b = g_rowptr[gw], e = g_rowptr[gw + 1];
                const float iv = g_inv[gw];
                const uint32_t* hp = (const uint32_t*)Hf;
                for (int j = b; j < e; j++) {
                    int s = g_col[j];
                    uint32_t u = hp[s * 32 + lane];
                    float2 a = __half22float2(*(const __half2*)&u);
                    acc.x += a.x; acc.y += a.y;
                }
                acc.x *= iv; acc.y *= iv;
            }
            uint32_t o;
            *(__half2*)&o = __floats2half2_rn(acc.x, acc.y);
            *(uint32_t*)&As[row * ASTR + lane * 2] = o;
        }
    }
    __syncthreads();

    // ---- phase 2: MMA over KT in BK=32 steps, B staged per step ----
    float c[2][8][4];
    #pragma unroll
    for (int mf = 0; mf < 2; mf++)
        #pragma unroll
        for (int nf = 0; nf < 8; nf++)
            #pragma unroll
            for (int j = 0; j < 4; j++) c[mf][nf][j] = 0.0f;

    const int frow = tid >> 1;
    const int foff = (tid & 1) * 16;

    #pragma unroll 1
    for (int kt = 0; kt < KT; kt += 32) {
        // stage B tile (128 n-rows x 32 halves)
        {
            const __half* p = W16 + (size_t)frow * 256 + kt + foff;
            *(uint4*)&Bs[frow * BS_STR + foff] = *(const uint4*)p;
            *(uint4*)&Bs[frow * BS_STR + foff + 8] = *(const uint4*)(p + 8);
        }
        __syncthreads();

        #pragma unroll
        for (int s = 0; s < 2; s++) {
            const int ak = kt + s * 16 + 2 * (lane & 3);
            const int bk = s * 16 + 2 * (lane & 3);
            const int arow = wm * 32 + (lane >> 2);
            uint32_t a[2][4];
            #pragma unroll
            for (int mf = 0; mf < 2; mf++) {
                int r = arow + mf * 16;
                a[mf][0] = *(const uint32_t*)&As[r * ASTR + ak];
                a[mf][1] = *(const uint32_t*)&As[(r + 8) * ASTR + ak];
                a[mf][2] = *(const uint32_t*)&As[r * ASTR + ak + 8];
                a[mf][3] = *(const uint32_t*)&As[(r + 8) * ASTR + ak + 8];
            }
            const int bn0 = wn2 * 64 + (lane >> 2);
            uint32_t bfr[8][2];
            #pragma unroll
            for (int nf = 0; nf < 8; nf++) {
                int n = bn0 + nf * 8;
                bfr[nf][0] = *(const uint32_t*)&Bs[n * BS_STR + bk];
                bfr[nf][1] = *(const uint32_t*)&Bs[n * BS_STR + bk + 8];
            }
            #pragma unroll
            for (int mf = 0; mf < 2; mf++) {
                #pragma unroll
                for (int nf = 0; nf < 8; nf++) {
                    asm volatile(
                        "mma.sync.aligned.m16n8k16.row.col.f32.f16.f16.f32 "
                        "{%0,%1,%2,%3}, {%4,%5,%6,%7}, {%8,%9}, {%0,%1,%2,%3};"
                        : "+f"(c[mf][nf][0]), "+f"(c[mf][nf][1]),
                          "+f"(c[mf][nf][2]), "+f"(c[mf][nf][3])
                        : "r"(a[mf][0]), "r"(a[mf][1]), "r"(a[mf][2]), "r"(a[mf][3]),
                          "r"(bfr[nf][0]), "r"(bfr[nf][1]));
                }
            }
        }
        __syncthreads();
    }

    // ---- epilogue: bias + activation + fp16 store ----
    const int colbase = wn2 * 64 + (lane & 3) * 2;
    float2 bb[8];
    #pragma unroll
    for (int nf = 0; nf < 8; nf++)
        bb[nf] = *(const float2*)(bias + colbase + nf * 8);

    #pragma unroll
    for (int mf = 0; mf < 2; mf++) {
        #pragma unroll
        for (int half = 0; half < 2; half++) {
            int m = m0 + wm * 32 + mf * 16 + (lane >> 2) + half * 8;
            if (m < NN) {
                __half* orow = Out + (size_t)m * CH;
                #pragma unroll
                for (int nf = 0; nf < 8; nf++) {
                    float vx = c[mf][nf][half * 2 + 0] + bb[nf].x;
                    float vy = c[mf][nf][half * 2 + 1] + bb[nf].y;
                    if (ACT == 1) {
                        vx = fmaxf(vx, 0.f);
                        vy = fmaxf(vy, 0.f);
                    } else if (ACT == 2) {
                        vx = (vx > 0.f) ? vx : NEG_SLOPE * vx;
                        vy = (vy > 0.f) ? vy : NEG_SLOPE * vy;
                    }
                    *(__half2*)(orow + colbase + nf * 8) = __floats2half2_rn(vx, vy);
                }
            }
        }
    }
}

// ---------------------------------------------------------------------------
// Global mean pool + linear head
// ---------------------------------------------------------------------------
__global__ void k_gcnt(const int* __restrict__ batch) {
    int i = blockIdx.x * blockDim.x + threadIdx.x;
    if (i < NN) atomicAdd(&g_gcnt[batch[i]], 1.0f);
}

__global__ void k_poolscatter16(const __half* __restrict__ h, const int* __restrict__ batch) {
    int i = blockIdx.x * blockDim.x + threadIdx.x;
    if (i >= NN * CH) return;
    int node = i >> 7;
    int c = i & 127;
    atomicAdd(&g_pool[batch[node] * CH + c], __half2float(h[i]));
}

__global__ void k_head(const float* __restrict__ hW, const float* __restrict__ hb,
                       float* __restrict__ out) {
    int g = blockIdx.x;
    int lane = threadIdx.x;
    float iv = 1.0f / fmaxf(g_gcnt[g], 1.0f);
    float a0 = 0.f, a1 = 0.f;
    for (int c = lane; c < CH; c += 32) {
        float p = g_pool[g * CH + c] * iv;
        a0 += p * hW[c * 2 + 0];
        a1 += p * hW[c * 2 + 1];
    }
    #pragma unroll
    for (int o = 16; o; o >>= 1) {
        a0 += __shfl_down_sync(0xffffffff, a0, o);
        a1 += __shfl_down_sync(0xffffffff, a1, o);
    }
    if (lane == 0) {
        out[g * 2 + 0] = a0 + hb[0];
        out[g * 2 + 1] = a1 + hb[1];
    }
}

// ---------------------------------------------------------------------------
// Host launch
// ---------------------------------------------------------------------------
static void* sym_addr(const void* sym) {
    void* p = nullptr;
    cudaGetSymbolAddress(&p, sym);
    return p;
}

#define SMEM_128 ((128 * (256 + 8) + 128 * BS_STR) * 2)
#define SMEM_64  ((128 * (128 + 8) + 128 * BS_STR) * 2)

extern "C" void kernel_launch(void* const* d_in, const int* in_sizes, int n_in,
                              void* d_out, int out_size) {
    const float* x    = (const float*)d_in[0];
    const int*   ei   = (const int*)d_in[1];
    const int*   srcp = ei;
    const int*   dstp = ei + EE;
    const int*   batch = (const int*)d_in[2];
    const float* Wl0 = (const float*)d_in[3];
    const float* Wr0 = (const float*)d_in[4];
    const float* b0  = (const float*)d_in[5];
    const float* Wl  = (const float*)d_in[6];
    const float* Wr  = (const float*)d_in[7];
    const float* bb  = (const float*)d_in[8];
    const float* hW  = (const float*)d_in[9];
    const float* hb  = (const float*)d_in[10];
    float* out = (float*)d_out;

    __half* h16A  = (__half*)sym_addr(g_h16A);
    __half* h16B  = (__half*)sym_addr(g_h16B);
    __half* x16   = (__half*)sym_addr(g_x16);
    __half* W16   = (__half*)sym_addr(g_W16);
    int*    deg   = (int*)sym_addr(g_deg);
    float*  pool  = (float*)sym_addr(g_pool);
    float*  gcnt  = (float*)sym_addr(g_gcnt);

    static int attr_set = 0;
    if (!attr_set) {
        cudaFuncSetAttribute(k_fused<64, 1>,  cudaFuncAttributeMaxDynamicSharedMemorySize, SMEM_64);
        cudaFuncSetAttribute(k_fused<128, 0>, cudaFuncAttributeMaxDynamicSharedMemorySize, SMEM_128);
        cudaFuncSetAttribute(k_fused<128, 1>, cudaFuncAttributeMaxDynamicSharedMemorySize, SMEM_128);
        cudaFuncSetAttribute(k_fused<128, 2>, cudaFuncAttributeMaxDynamicSharedMemorySize, SMEM_128);
        attr_set = 1;
    }

    const int TPB = 256;

    // --- CSR build + fp16 conversions (inside the graph, once per launch) ---
    k_zero_i<<<(NN + TPB - 1) / TPB, TPB>>>(deg, NN);
    k_count<<<(EE + TPB - 1) / TPB, TPB>>>(dstp);
    k_cvt_x<<<(NN * CIN + TPB - 1) / TPB, TPB>>>(x);
    k_w16<<<(12 * 128 * 256 + TPB - 1) / TPB, TPB>>>(Wl0, Wr0, Wl, Wr);
    k_scan<<<1, 1024>>>();
    k_fill<<<(EE + TPB - 1) / TPB, TPB>>>(srcp, dstp);

    // --- conv 0 (C_IN=64 -> 128), ReLU ---
    k_fused<64, 1><<<GEMM_BLOCKS, TPB, SMEM_64>>>(x16, W16, b0, h16A);

    // --- convs 1..11 ---
    __half* hcur = h16A;
    __half* hnxt = h16B;
    for (int i = 0; i < 11; i++) {
        int ci = i + 1;
        const __half* wt = W16 + (size_t)(i + 1) * 128 * 256;
        const float* bi = bb + (size_t)i * CH;
        if (ci == 11) {
            k_fused<128, 0><<<GEMM_BLOCKS, TPB, SMEM_128>>>(hcur, wt, bi, hnxt);
        } else if (ci == 3 || ci == 7) {
            k_fused<128, 2><<<GEMM_BLOCKS, TPB, SMEM_128>>>(hcur, wt, bi, hnxt);
        } else {
            k_fused<128, 1><<<GEMM_BLOCKS, TPB, SMEM_128>>>(hcur, wt, bi, hnxt);
        }
        __half* t = hcur; hcur = hnxt; hnxt = t;
    }

    // --- global mean pool + head ---
    k_zero_f<<<(GG * CH + TPB - 1) / TPB, TPB>>>(pool, GG * CH);
    k_zero_f<<<(GG + TPB - 1) / TPB, TPB>>>(gcnt, GG);
    k_gcnt<<<(NN + TPB - 1) / TPB, TPB>>>(batch);
    k_poolscatter16<<<(NN * CH + TPB - 1) / TPB, TPB>>>(hcur, batch);
    k_head<<<GG, 32>>>(hW, hb, out);
}

// round 9
// speedup vs baseline: 1.4892x; 1.4892x over previous
#include <cuda_runtime.h>
#include <cuda_fp16.h>
#include <cstddef>
#include <cstdint>

// Problem constants (fixed by the dataset)
#define NN   50000
#define EE   800000
#define GG   512
#define CH   128
#define CIN  64
#define NEG_SLOPE 0.01f

#define TILE_M 128
#define GEMM_BLOCKS ((NN + TILE_M - 1) / TILE_M)

// ---------------------------------------------------------------------------
// Device-global scratch
// ---------------------------------------------------------------------------
__device__ __half g_h16A[NN * CH];
__device__ __half g_h16B[NN * CH];
__device__ __half g_agg16[NN * CH];
__device__ __half g_x16[NN * CIN];
__device__ __half g_W16[12 * 128 * 256];   // [layer][n=128][k=256]
__device__ float g_inv[NN];
__device__ int   g_deg[NN];
__device__ int   g_rowptr[NN + 1];
__device__ int   g_cursor[NN];
__device__ int   g_col[EE];
__device__ int   g_gstart[GG + 1];

// ---------------------------------------------------------------------------
// Utility kernels
// ---------------------------------------------------------------------------
__global__ void k_zero_i(int* p, int n) {
    int i = blockIdx.x * blockDim.x + threadIdx.x;
    if (i < n) p[i] = 0;
}
__global__ void k_count(const int* __restrict__ dst) {
    int i = blockIdx.x * blockDim.x + threadIdx.x;
    if (i < EE) atomicAdd(&g_deg[dst[i]], 1);
}

// One-pass scan: 1024 threads, thread t owns 49 contiguous elements.
__global__ void k_scan2() {
    const int NPT = 49;  // 1024*49 = 50176 >= NN
    const int tid = threadIdx.x;
    const int base = tid * NPT;
    int sum = 0;
    #pragma unroll 1
    for (int j = 0; j < NPT; j++) {
        int i = base + j;
        if (i < NN) sum += g_deg[i];
    }
    const int lane = tid & 31, w = tid >> 5;
    int s = sum;
    #pragma unroll
    for (int o = 1; o < 32; o <<= 1) {
        int t = __shfl_up_sync(0xffffffffu, s, o);
        if (lane >= o) s += t;
    }
    __shared__ int wsum[32];
    if (lane == 31) wsum[w] = s;
    __syncthreads();
    if (w == 0) {
        int ws = wsum[lane];
        #pragma unroll
        for (int o = 1; o < 32; o <<= 1) {
            int t = __shfl_up_sync(0xffffffffu, ws, o);
            if (lane >= o) ws += t;
        }
        wsum[lane] = ws;
    }
    __syncthreads();
    int run = s - sum + (w > 0 ? wsum[w - 1] : 0);
    #pragma unroll 1
    for (int j = 0; j < NPT; j++) {
        int i = base + j;
        if (i < NN) {
            int v = g_deg[i];
            g_rowptr[i] = run;
            g_cursor[i] = run;
            g_inv[i] = 1.0f / (float)max(v, 1);
            run += v;
        }
    }
    if (tid == 1023) g_rowptr[NN] = run;  // base >= NN so run == total
}

__global__ void k_fill(const int* __restrict__ src, const int* __restrict__ dst) {
    int i = blockIdx.x * blockDim.x + threadIdx.x;
    if (i < EE) {
        int d = dst[i];
        int pos = atomicAdd(&g_cursor[d], 1);
        g_col[pos] = src[i];
    }
}

// Graph boundaries via binary search (batch_idx is sorted)
__global__ void k_gstart(const int* __restrict__ batch) {
    int g = blockIdx.x * blockDim.x + threadIdx.x;
    if (g > GG) return;
    int lo = 0, hi = NN;
    while (lo < hi) {
        int mid = (lo + hi) >> 1;
        if (batch[mid] < g) lo = mid + 1; else hi = mid;
    }
    g_gstart[g] = lo;
}

// Convert input features x (fp32) -> fp16
__global__ void k_cvt_x(const float* __restrict__ x) {
    int i = blockIdx.x * blockDim.x + threadIdx.x;
    if (i < NN * CIN) g_x16[i] = __float2half_rn(x[i]);
}

// Build transposed fp16 weight table: g_W16[l][n][k] = Wcat_l[k][n]
__global__ void k_w16(const float* __restrict__ Wl0, const float* __restrict__ Wr0,
                      const float* __restrict__ Wl, const float* __restrict__ Wr) {
    int idx = blockIdx.x * blockDim.x + threadIdx.x;
    if (idx >= 12 * 128 * 256) return;
    int l = idx >> 15;
    int n = (idx >> 8) & 127;
    int k = idx & 255;
    float v = 0.0f;
    if (l == 0) {
        if (k < 64)       v = Wl0[k * 128 + n];
        else if (k < 128) v = Wr0[(k - 64) * 128 + n];
    } else {
        int i = l - 1;
        if (k < 128) v = Wl[(size_t)i * 128 * 128 + k * 128 + n];
        else         v = Wr[(size_t)i * 128 * 128 + (k - 128) * 128 + n];
    }
    g_W16[idx] = __float2half_rn(v);
}

// ---------------------------------------------------------------------------
// Mean aggregation (fp16 in/out, fp32 accumulate): one warp per node.
// 2-way unrolled accumulators to shorten the FADD dependency chain.
// ---------------------------------------------------------------------------
template <int C>
__global__ void k_agg16(const __half* __restrict__ h, __half* __restrict__ agg) {
    int gw = (blockIdx.x * blockDim.x + threadIdx.x) >> 5;
    if (gw >= NN) return;
    int lane = threadIdx.x & 31;
    int b = g_rowptr[gw], e = g_rowptr[gw + 1];
    float iv = g_inv[gw];
    if constexpr (C == 128) {
        const uint2* hp = (const uint2*)h;
        float4 a0 = make_float4(0.f, 0.f, 0.f, 0.f);
        float4 a1 = make_float4(0.f, 0.f, 0.f, 0.f);
        int j = b;
        for (; j + 1 < e; j += 2) {
            int s0 = g_col[j], s1 = g_col[j + 1];
            uint2 u0 = hp[s0 * 32 + lane];
            uint2 u1 = hp[s1 * 32 + lane];
            float2 p0 = __half22float2(*(const __half2*)&u0.x);
            float2 q0 = __half22float2(*(const __half2*)&u0.y);
            float2 p1 = __half22float2(*(const __half2*)&u1.x);
            float2 q1 = __half22float2(*(const __half2*)&u1.y);
            a0.x += p0.x; a0.y += p0.y; a0.z += q0.x; a0.w += q0.y;
            a1.x += p1.x; a1.y += p1.y; a1.z += q1.x; a1.w += q1.y;
        }
        if (j < e) {
            int s0 = g_col[j];
            uint2 u0 = hp[s0 * 32 + lane];
            float2 p0 = __half22float2(*(const __half2*)&u0.x);
            float2 q0 = __half22float2(*(const __half2*)&u0.y);
            a0.x += p0.x; a0.y += p0.y; a0.z += q0.x; a0.w += q0.y;
        }
        a0.x = (a0.x + a1.x) * iv; a0.y = (a0.y + a1.y) * iv;
        a0.z = (a0.z + a1.z) * iv; a0.w = (a0.w + a1.w) * iv;
        uint2 o;
        *(__half2*)&o.x = __floats2half2_rn(a0.x, a0.y);
        *(__half2*)&o.y = __floats2half2_rn(a0.z, a0.w);
        ((uint2*)agg)[gw * 32 + lane] = o;
    } else {  // C == 64
        const uint32_t* hp = (const uint32_t*)h;
        float2 a0 = make_float2(0.f, 0.f), a1 = make_float2(0.f, 0.f);
        int j = b;
        for (; j + 1 < e; j += 2) {
            int s0 = g_col[j], s1 = g_col[j + 1];
            uint32_t u0 = hp[s0 * 32 + lane];
            uint32_t u1 = hp[s1 * 32 + lane];
            float2 p0 = __half22float2(*(const __half2*)&u0);
            float2 p1 = __half22float2(*(const __half2*)&u1);
            a0.x += p0.x; a0.y += p0.y;
            a1.x += p1.x; a1.y += p1.y;
        }
        if (j < e) {
            uint32_t u0 = hp[g_col[j] * 32 + lane];
            float2 p0 = __half22float2(*(const __half2*)&u0);
            a0.x += p0.x; a0.y += p0.y;
        }
        a0.x = (a0.x + a1.x) * iv; a0.y = (a0.y + a1.y) * iv;
        uint32_t o;
        *(__half2*)&o = __floats2half2_rn(a0.x, a0.y);
        ((uint32_t*)agg)[gw * 32 + lane] = o;
    }
}

// ---------------------------------------------------------------------------
// fp16 mma.sync fused SAGEConv GEMM with cp.async double buffering.
//   Out[m][n] = [agg16[m] | h16[m]] @ W16_l^T + bias[n], activation applied.
// KT = 2*KH. BM=128, BN=128, BK=32. 256 threads, 8 warps (4m x 2n).
// ---------------------------------------------------------------------------
#define AS_STR 40
#define BS_STR 40

__device__ __forceinline__ void cp16(uint32_t dst, const void* src) {
    asm volatile("cp.async.ca.shared.global [%0], [%1], 16;" :: "r"(dst), "l"(src));
}
#define CP_COMMIT() asm volatile("cp.async.commit_group;" ::: "memory")
template <int Nw>
__device__ __forceinline__ void cp_wait() {
    asm volatile("cp.async.wait_group %0;" :: "n"(Nw) : "memory");
}

template <int KH, int ACT>
__global__ __launch_bounds__(256) void k_gemm16(
    const __half* __restrict__ A,    // aggregated fp16, [NN][KH]
    const __half* __restrict__ H,    // node features fp16, [NN][KH]
    const __half* __restrict__ W16,  // [128][256] transposed fp16 weights (layer)
    const float* __restrict__ bias,  // [128]
    __half* __restrict__ Out)        // [NN][128]
{
    constexpr int KT = 2 * KH;
    constexpr int NIT = KT / 32;
    __shared__ __half As[2][128 * AS_STR];
    __shared__ __half Bs[2][128 * BS_STR];

    const int tid = threadIdx.x;
    const int wid = tid >> 5;
    const int lane = tid & 31;
    const int wm = wid & 3;
    const int wn2 = wid >> 2;
    const int m0 = blockIdx.x * TILE_M;

    // cp.async issue: 512 16B chunks per operand, 2 per thread
    const int c0 = tid, c1 = tid + 256;

    auto issue = [&](int stg, int kt) {
        #pragma unroll
        for (int cc = 0; cc < 2; cc++) {
            int c = (cc == 0) ? c0 : c1;
            int r = c >> 2, part = c & 3;
            // A chunk
            {
                int m = m0 + r;
                int mm = (m < NN) ? m : (NN - 1);   // clamp; garbage rows discarded
                int kcat = kt + part * 8;
                const __half* p = (kcat < KH) ? (A + (size_t)mm * KH + kcat)
                                              : (H + (size_t)mm * KH + (kcat - KH));
                uint32_t d = (uint32_t)__cvta_generic_to_shared(&As[stg][r * AS_STR + part * 8]);
                cp16(d, p);
            }
            // B chunk
            {
                const __half* p = W16 + (size_t)r * 256 + kt + part * 8;
                uint32_t d = (uint32_t)__cvta_generic_to_shared(&Bs[stg][r * BS_STR + part * 8]);
                cp16(d, p);
            }
        }
    };

    float c[2][8][4];
    #pragma unroll
    for (int mf = 0; mf < 2; mf++)
        #pragma unroll
        for (int nf = 0; nf < 8; nf++)
            #pragma unroll
            for (int j = 0; j < 4; j++) c[mf][nf][j] = 0.0f;

    issue(0, 0);
    CP_COMMIT();

    #pragma unroll 1
    for (int it = 0; it < NIT; it++) {
        if (it + 1 < NIT) {
            issue((it + 1) & 1, (it + 1) * 32);
            CP_COMMIT();
            cp_wait<1>();
        } else {
            cp_wait<0>();
        }
        __syncthreads();

        const int stg = it & 1;
        const __half* Asb = As[stg];
        const __half* Bsb = Bs[stg];

        #pragma unroll
        for (int s = 0; s < 2; s++) {
            const int ak = s * 16 + 2 * (lane & 3);
            const int arow = wm * 32 + (lane >> 2);
            uint32_t a[2][4];
            #pragma unroll
            for (int mf = 0; mf < 2; mf++) {
                int r = arow + mf * 16;
                a[mf][0] = *(const uint32_t*)&Asb[r * AS_STR + ak];
                a[mf][1] = *(const uint32_t*)&Asb[(r + 8) * AS_STR + ak];
                a[mf][2] = *(const uint32_t*)&Asb[r * AS_STR + ak + 8];
                a[mf][3] = *(const uint32_t*)&Asb[(r + 8) * AS_STR + ak + 8];
            }
            const int bn0 = wn2 * 64 + (lane >> 2);
            uint32_t bfr[8][2];
            #pragma unroll
            for (int nf = 0; nf < 8; nf++) {
                int n = bn0 + nf * 8;
                bfr[nf][0] = *(const uint32_t*)&Bsb[n * BS_STR + ak];
                bfr[nf][1] = *(const uint32_t*)&Bsb[n * BS_STR + ak + 8];
            }
            #pragma unroll
            for (int mf = 0; mf < 2; mf++) {
                #pragma unroll
                for (int nf = 0; nf < 8; nf++) {
                    asm volatile(
                        "mma.sync.aligned.m16n8k16.row.col.f32.f16.f16.f32 "
                        "{%0,%1,%2,%3}, {%4,%5,%6,%7}, {%8,%9}, {%0,%1,%2,%3};"
                        : "+f"(c[mf][nf][0]), "+f"(c[mf][nf][1]),
                          "+f"(c[mf][nf][2]), "+f"(c[mf][nf][3])
                        : "r"(a[mf][0]), "r"(a[mf][1]), "r"(a[mf][2]), "r"(a[mf][3]),
                          "r"(bfr[nf][0]), "r"(bfr[nf][1]));
                }
            }
        }
        __syncthreads();
    }

    // ---- epilogue: bias + activation + fp16 store ----
    const int colbase = wn2 * 64 + (lane & 3) * 2;
    float2 bb[8];
    #pragma unroll
    for (int nf = 0; nf < 8; nf++)
        bb[nf] = *(const float2*)(bias + colbase + nf * 8);

    #pragma unroll
    for (int mf = 0; mf < 2; mf++) {
        #pragma unroll
        for (int half = 0; half < 2; half++) {
            int m = m0 + wm * 32 + mf * 16 + (lane >> 2) + half * 8;
            if (m < NN) {
                __half* orow = Out + (size_t)m * CH;
                #pragma unroll
                for (int nf = 0; nf < 8; nf++) {
                    float vx = c[mf][nf][half * 2 + 0] + bb[nf].x;
                    float vy = c[mf][nf][half * 2 + 1] + bb[nf].y;
                    if (ACT == 1) {
                        vx = fmaxf(vx, 0.f);
                        vy = fmaxf(vy, 0.f);
                    } else if (ACT == 2) {
                        vx = (vx > 0.f) ? vx : NEG_SLOPE * vx;
                        vy = (vy > 0.f) ? vy : NEG_SLOPE * vy;
                    }
                    *(__half2*)(orow + colbase + nf * 8) = __floats2half2_rn(vx, vy);
                }
            }
        }
    }
}

// ---------------------------------------------------------------------------
// Fused segment-mean pool + linear head: one block per graph (batch sorted).
// ---------------------------------------------------------------------------
__global__ void k_poolhead(const __half* __restrict__ h,
                           const float* __restrict__ hW, const float* __restrict__ hb,
                           float* __restrict__ out) {
    const int g = blockIdx.x;
    const int t = threadIdx.x;    // channel, 0..127
    const int s = g_gstart[g], e = g_gstart[g + 1];
    float acc = 0.f;
    for (int i = s; i < e; i++)
        acc += __half2float(h[(size_t)i * CH + t]);
    const float iv = 1.0f / (float)max(e - s, 1);
    const float p = acc * iv;
    __shared__ float r0[128], r1[128];
    r0[t] = p * hW[t * 2 + 0];
    r1[t] = p * hW[t * 2 + 1];
    __syncthreads();
    #pragma unroll
    for (int o = 64; o > 0; o >>= 1) {
        if (t < o) { r0[t] += r0[t + o]; r1[t] += r1[t + o]; }
        __syncthreads();
    }
    if (t == 0) {
        out[g * 2 + 0] = r0[0] + hb[0];
        out[g * 2 + 1] = r1[0] + hb[1];
    }
}

// ---------------------------------------------------------------------------
// Host launch
// ---------------------------------------------------------------------------
static void* sym_addr(const void* sym) {
    void* p = nullptr;
    cudaGetSymbolAddress(&p, sym);
    return p;
}

extern "C" void kernel_launch(void* const* d_in, const int* in_sizes, int n_in,
                              void* d_out, int out_size) {
    const float* x    = (const float*)d_in[0];
    const int*   ei   = (const int*)d_in[1];
    const int*   srcp = ei;
    const int*   dstp = ei + EE;
    const int*   batch = (const int*)d_in[2];
    const float* Wl0 = (const float*)d_in[3];
    const float* Wr0 = (const float*)d_in[4];
    const float* b0  = (const float*)d_in[5];
    const float* Wl  = (const float*)d_in[6];
    const float* Wr  = (const float*)d_in[7];
    const float* bb  = (const float*)d_in[8];
    const float* hW  = (const float*)d_in[9];
    const float* hb  = (const float*)d_in[10];
    float* out = (float*)d_out;

    __half* h16A  = (__half*)sym_addr(g_h16A);
    __half* h16B  = (__half*)sym_addr(g_h16B);
    __half* agg16 = (__half*)sym_addr(g_agg16);
    __half* x16   = (__half*)sym_addr(g_x16);
    __half* W16   = (__half*)sym_addr(g_W16);
    int*    deg   = (int*)sym_addr(g_deg);

    const int TPB = 256;

    // --- CSR build + fp16 conversions + graph bounds ---
    k_zero_i<<<(NN + TPB - 1) / TPB, TPB>>>(deg, NN);
    k_count<<<(EE + TPB - 1) / TPB, TPB>>>(dstp);
    k_cvt_x<<<(NN * CIN + TPB - 1) / TPB, TPB>>>(x);
    k_w16<<<(12 * 128 * 256 + TPB - 1) / TPB, TPB>>>(Wl0, Wr0, Wl, Wr);
    k_gstart<<<3, 256>>>(batch);
    k_scan2<<<1, 1024>>>();
    k_fill<<<(EE + TPB - 1) / TPB, TPB>>>(srcp, dstp);

    const int aggBlocks = (NN * 32 + TPB - 1) / TPB;

    // --- conv 0 (C_IN=64 -> 128), ReLU ---
    k_agg16<64><<<aggBlocks, TPB>>>(x16, agg16);
    k_gemm16<64, 1><<<GEMM_BLOCKS, TPB>>>(agg16, x16, W16, b0, h16A);

    // --- convs 1..11 ---
    __half* hcur = h16A;
    __half* hnxt = h16B;
    for (int i = 0; i < 11; i++) {
        int ci = i + 1;
        k_agg16<128><<<aggBlocks, TPB>>>(hcur, agg16);
        const __half* wt = W16 + (size_t)(i + 1) * 128 * 256;
        const float* bi = bb + (size_t)i * CH;
        if (ci == 11) {
            k_gemm16<128, 0><<<GEMM_BLOCKS, TPB>>>(agg16, hcur, wt, bi, hnxt);
        } else if (ci == 3 || ci == 7) {
            k_gemm16<128, 2><<<GEMM_BLOCKS, TPB>>>(agg16, hcur, wt, bi, hnxt);
        } else {
            k_gemm16<128, 1><<<GEMM_BLOCKS, TPB>>>(agg16, hcur, wt, bi, hnxt);
        }
        __half* t = hcur; hcur = hnxt; hnxt = t;
    }

    // --- fused global mean pool + head ---
    k_poolhead<<<GG, 128>>>(hcur, hW, hb, out);
}

// round 10
// speedup vs baseline: 1.4901x; 1.0006x over previous
#include <cuda_runtime.h>
#include <cuda_fp16.h>
#include <cstddef>
#include <cstdint>

// Problem constants (fixed by the dataset)
#define NN   50000
#define EE   800000
#define GG   512
#define CH   128
#define CIN  64
#define NEG_SLOPE 0.01f

#define TILE_M 128
#define GEMM_BLOCKS ((NN + TILE_M - 1) / TILE_M)

// ---------------------------------------------------------------------------
// Device-global scratch
// ---------------------------------------------------------------------------
__device__ __half g_h16A[NN * CH];
__device__ __half g_h16B[NN * CH];
__device__ __half g_agg16[NN * CH];
__device__ __half g_x16[NN * CIN];
__device__ __half g_W16[12 * 128 * 256];   // [layer][n=128][k=256]
__device__ float g_inv[NN];
__device__ int   g_deg[NN];
__device__ int   g_rowptr[NN + 1];
__device__ int   g_cursor[NN];
__device__ int   g_col[EE];
__device__ int   g_gstart[GG + 1];

// ---------------------------------------------------------------------------
// Utility kernels
// ---------------------------------------------------------------------------
__global__ void k_zero_i(int* p, int n) {
    int i = blockIdx.x * blockDim.x + threadIdx.x;
    if (i < n) p[i] = 0;
}
__global__ void k_count(const int* __restrict__ dst) {
    int i = blockIdx.x * blockDim.x + threadIdx.x;
    if (i < EE) atomicAdd(&g_deg[dst[i]], 1);
}

// One-pass scan: 1024 threads, thread t owns 49 contiguous elements.
__global__ void k_scan2() {
    const int NPT = 49;  // 1024*49 = 50176 >= NN
    const int tid = threadIdx.x;
    const int base = tid * NPT;
    int sum = 0;
    #pragma unroll 1
    for (int j = 0; j < NPT; j++) {
        int i = base + j;
        if (i < NN) sum += g_deg[i];
    }
    const int lane = tid & 31, w = tid >> 5;
    int s = sum;
    #pragma unroll
    for (int o = 1; o < 32; o <<= 1) {
        int t = __shfl_up_sync(0xffffffffu, s, o);
        if (lane >= o) s += t;
    }
    __shared__ int wsum[32];
    if (lane == 31) wsum[w] = s;
    __syncthreads();
    if (w == 0) {
        int ws = wsum[lane];
        #pragma unroll
        for (int o = 1; o < 32; o <<= 1) {
            int t = __shfl_up_sync(0xffffffffu, ws, o);
            if (lane >= o) ws += t;
        }
        wsum[lane] = ws;
    }
    __syncthreads();
    int run = s - sum + (w > 0 ? wsum[w - 1] : 0);
    #pragma unroll 1
    for (int j = 0; j < NPT; j++) {
        int i = base + j;
        if (i < NN) {
            int v = g_deg[i];
            g_rowptr[i] = run;
            g_cursor[i] = run;
            g_inv[i] = 1.0f / (float)max(v, 1);
            run += v;
        }
    }
    if (tid == 1023) g_rowptr[NN] = run;
}

__global__ void k_fill(const int* __restrict__ src, const int* __restrict__ dst) {
    int i = blockIdx.x * blockDim.x + threadIdx.x;
    if (i < EE) {
        int d = dst[i];
        int pos = atomicAdd(&g_cursor[d], 1);
        g_col[pos] = src[i];
    }
}

// Graph boundaries via binary search (batch_idx is sorted)
__global__ void k_gstart(const int* __restrict__ batch) {
    int g = blockIdx.x * blockDim.x + threadIdx.x;
    if (g > GG) return;
    int lo = 0, hi = NN;
    while (lo < hi) {
        int mid = (lo + hi) >> 1;
        if (batch[mid] < g) lo = mid + 1; else hi = mid;
    }
    g_gstart[g] = lo;
}

// Combined: convert x fp32->fp16 AND build transposed fp16 weight table.
__global__ void k_prep(const float* __restrict__ x,
                       const float* __restrict__ Wl0, const float* __restrict__ Wr0,
                       const float* __restrict__ Wl, const float* __restrict__ Wr) {
    int i = blockIdx.x * blockDim.x + threadIdx.x;
    if (i < NN * CIN) g_x16[i] = __float2half_rn(x[i]);
    if (i < 12 * 128 * 256) {
        int l = i >> 15;
        int n = (i >> 8) & 127;
        int k = i & 255;
        float v = 0.0f;
        if (l == 0) {
            if (k < 64)       v = Wl0[k * 128 + n];
            else if (k < 128) v = Wr0[(k - 64) * 128 + n];
        } else {
            int li = l - 1;
            if (k < 128) v = Wl[(size_t)li * 128 * 128 + k * 128 + n];
            else         v = Wr[(size_t)li * 128 * 128 + (k - 128) * 128 + n];
        }
        g_W16[i] = __float2half_rn(v);
    }
}

// ---------------------------------------------------------------------------
// Mean aggregation (fp16 in/out, fp32 accumulate): one warp per node.
// ---------------------------------------------------------------------------
template <int C>
__global__ void k_agg16(const __half* __restrict__ h, __half* __restrict__ agg) {
    int gw = (blockIdx.x * blockDim.x + threadIdx.x) >> 5;
    if (gw >= NN) return;
    int lane = threadIdx.x & 31;
    int b = g_rowptr[gw], e = g_rowptr[gw + 1];
    float iv = g_inv[gw];
    if constexpr (C == 128) {
        const uint2* hp = (const uint2*)h;
        float4 a0 = make_float4(0.f, 0.f, 0.f, 0.f);
        float4 a1 = make_float4(0.f, 0.f, 0.f, 0.f);
        int j = b;
        for (; j + 1 < e; j += 2) {
            int s0 = g_col[j], s1 = g_col[j + 1];
            uint2 u0 = hp[s0 * 32 + lane];
            uint2 u1 = hp[s1 * 32 + lane];
            float2 p0 = __half22float2(*(const __half2*)&u0.x);
            float2 q0 = __half22float2(*(const __half2*)&u0.y);
            float2 p1 = __half22float2(*(const __half2*)&u1.x);
            float2 q1 = __half22float2(*(const __half2*)&u1.y);
            a0.x += p0.x; a0.y += p0.y; a0.z += q0.x; a0.w += q0.y;
            a1.x += p1.x; a1.y += p1.y; a1.z += q1.x; a1.w += q1.y;
        }
        if (j < e) {
            int s0 = g_col[j];
            uint2 u0 = hp[s0 * 32 + lane];
            float2 p0 = __half22float2(*(const __half2*)&u0.x);
            float2 q0 = __half22float2(*(const __half2*)&u0.y);
            a0.x += p0.x; a0.y += p0.y; a0.z += q0.x; a0.w += q0.y;
        }
        a0.x = (a0.x + a1.x) * iv; a0.y = (a0.y + a1.y) * iv;
        a0.z = (a0.z + a1.z) * iv; a0.w = (a0.w + a1.w) * iv;
        uint2 o;
        *(__half2*)&o.x = __floats2half2_rn(a0.x, a0.y);
        *(__half2*)&o.y = __floats2half2_rn(a0.z, a0.w);
        ((uint2*)agg)[gw * 32 + lane] = o;
    } else {  // C == 64
        const uint32_t* hp = (const uint32_t*)h;
        float2 a0 = make_float2(0.f, 0.f), a1 = make_float2(0.f, 0.f);
        int j = b;
        for (; j + 1 < e; j += 2) {
            int s0 = g_col[j], s1 = g_col[j + 1];
            uint32_t u0 = hp[s0 * 32 + lane];
            uint32_t u1 = hp[s1 * 32 + lane];
            float2 p0 = __half22float2(*(const __half2*)&u0);
            float2 p1 = __half22float2(*(const __half2*)&u1);
            a0.x += p0.x; a0.y += p0.y;
            a1.x += p1.x; a1.y += p1.y;
        }
        if (j < e) {
            uint32_t u0 = hp[g_col[j] * 32 + lane];
            float2 p0 = __half22float2(*(const __half2*)&u0);
            a0.x += p0.x; a0.y += p0.y;
        }
        a0.x = (a0.x + a1.x) * iv; a0.y = (a0.y + a1.y) * iv;
        uint32_t o;
        *(__half2*)&o = __floats2half2_rn(a0.x, a0.y);
        ((uint32_t*)agg)[gw * 32 + lane] = o;
    }
}

// ---------------------------------------------------------------------------
// fp16 mma.sync GEMM, cp.async double-buffered, ldmatrix fragment loads.
// ---------------------------------------------------------------------------
#define AS_STR 40
#define BS_STR 40

__device__ __forceinline__ void cp16(uint32_t dst, const void* src) {
    asm volatile("cp.async.ca.shared.global [%0], [%1], 16;" :: "r"(dst), "l"(src));
}
#define CP_COMMIT() asm volatile("cp.async.commit_group;" ::: "memory")
template <int Nw>
__device__ __forceinline__ void cp_wait() {
    asm volatile("cp.async.wait_group %0;" :: "n"(Nw) : "memory");
}
__device__ __forceinline__ void ldsm4(uint32_t& r0, uint32_t& r1, uint32_t& r2,
                                      uint32_t& r3, uint32_t addr) {
    asm volatile("ldmatrix.sync.aligned.m8n8.x4.shared.b16 {%0,%1,%2,%3}, [%4];"
                 : "=r"(r0), "=r"(r1), "=r"(r2), "=r"(r3) : "r"(addr));
}

template <int KH, int ACT>
__global__ __launch_bounds__(256) void k_gemm16(
    const __half* __restrict__ A,    // aggregated fp16, [NN][KH]
    const __half* __restrict__ H,    // node features fp16, [NN][KH]
    const __half* __restrict__ W16,  // [128][256] transposed fp16 weights (layer)
    const float* __restrict__ bias,  // [128]
    __half* __restrict__ Out)        // [NN][128]
{
    constexpr int KT = 2 * KH;
    constexpr int NIT = KT / 32;
    __shared__ __half As[2][128 * AS_STR];
    __shared__ __half Bs[2][128 * BS_STR];

    const int tid = threadIdx.x;
    const int wid = tid >> 5;
    const int lane = tid & 31;
    const int wm = wid & 3;
    const int wn2 = wid >> 2;
    const int m0 = blockIdx.x * TILE_M;

    const int c0 = tid, c1 = tid + 256;

    auto issue = [&](int stg, int kt) {
        #pragma unroll
        for (int cc = 0; cc < 2; cc++) {
            int cch = (cc == 0) ? c0 : c1;
            int r = cch >> 2, part = cch & 3;
            {
                int m = m0 + r;
                int mm = (m < NN) ? m : (NN - 1);
                int kcat = kt + part * 8;
                const __half* p = (kcat < KH) ? (A + (size_t)mm * KH + kcat)
                                              : (H + (size_t)mm * KH + (kcat - KH));
                uint32_t d = (uint32_t)__cvta_generic_to_shared(&As[stg][r * AS_STR + part * 8]);
                cp16(d, p);
            }
            {
                const __half* p = W16 + (size_t)r * 256 + kt + part * 8;
                uint32_t d = (uint32_t)__cvta_generic_to_shared(&Bs[stg][r * BS_STR + part * 8]);
                cp16(d, p);
            }
        }
    };

    float c[2][8][4];
    #pragma unroll
    for (int mf = 0; mf < 2; mf++)
        #pragma unroll
        for (int nf = 0; nf < 8; nf++)
            #pragma unroll
            for (int j = 0; j < 4; j++) c[mf][nf][j] = 0.0f;

    issue(0, 0);
    CP_COMMIT();

    const int l7 = lane & 7;
    const int g = lane >> 3;
    const int aRowOff = (g & 1) * 8;   // A: +8 rows for odd groups
    const int aKOff   = (g & 2) * 4;   // A: +8 k for groups 2,3
    const int bNOff   = (g & 2) * 4;   // B: +8 n for groups 2,3
    const int bKOff   = (g & 1) * 8;   // B: +8 k for odd groups

    #pragma unroll 1
    for (int it = 0; it < NIT; it++) {
        if (it + 1 < NIT) {
            issue((it + 1) & 1, (it + 1) * 32);
            CP_COMMIT();
            cp_wait<1>();
        } else {
            cp_wait<0>();
        }
        __syncthreads();

        const int stg = it & 1;
        const uint32_t aBase = (uint32_t)__cvta_generic_to_shared(&As[stg][0]);
        const uint32_t bBase = (uint32_t)__cvta_generic_to_shared(&Bs[stg][0]);

        #pragma unroll
        for (int s = 0; s < 2; s++) {
            const int kb = s * 16;
            uint32_t a[2][4];
            #pragma unroll
            for (int mf = 0; mf < 2; mf++) {
                int row = wm * 32 + mf * 16 + l7 + aRowOff;
                uint32_t addr = aBase + (uint32_t)(row * AS_STR + kb + aKOff) * 2;
                ldsm4(a[mf][0], a[mf][1], a[mf][2], a[mf][3], addr);
            }
            uint32_t bfr[8][2];
            #pragma unroll
            for (int p = 0; p < 4; p++) {
                int n = wn2 * 64 + p * 16 + l7 + bNOff;
                uint32_t addr = bBase + (uint32_t)(n * BS_STR + kb + bKOff) * 2;
                ldsm4(bfr[2 * p][0], bfr[2 * p][1], bfr[2 * p + 1][0], bfr[2 * p + 1][1], addr);
            }
            #pragma unroll
            for (int mf = 0; mf < 2; mf++) {
                #pragma unroll
                for (int nf = 0; nf < 8; nf++) {
                    asm volatile(
                        "mma.sync.aligned.m16n8k16.row.col.f32.f16.f16.f32 "
                        "{%0,%1,%2,%3}, {%4,%5,%6,%7}, {%8,%9}, {%0,%1,%2,%3};"
                        : "+f"(c[mf][nf][0]), "+f"(c[mf][nf][1]),
                          "+f"(c[mf][nf][2]), "+f"(c[mf][nf][3])
                        : "r"(a[mf][0]), "r"(a[mf][1]), "r"(a[mf][2]), "r"(a[mf][3]),
                          "r"(bfr[nf][0]), "r"(bfr[nf][1]));
                }
            }
        }
        __syncthreads();
    }

    // ---- epilogue: bias + activation + fp16 store ----
    const int colbase = wn2 * 64 + (lane & 3) * 2;
    float2 bb[8];
    #pragma unroll
    for (int nf = 0; nf < 8; nf++)
        bb[nf] = *(const float2*)(bias + colbase + nf * 8);

    #pragma unroll
    for (int mf = 0; mf < 2; mf++) {
        #pragma unroll
        for (int half = 0; half < 2; half++) {
            int m = m0 + wm * 32 + mf * 16 + (lane >> 2) + half * 8;
            if (m < NN) {
                __half* orow = Out + (size_t)m * CH;
                #pragma unroll
                for (int nf = 0; nf < 8; nf++) {
                    float vx = c[mf][nf][half * 2 + 0] + bb[nf].x;
                    float vy = c[mf][nf][half * 2 + 1] + bb[nf].y;
                    if (ACT == 1) {
                        vx = fmaxf(vx, 0.f);
                        vy = fmaxf(vy, 0.f);
                    } else if (ACT == 2) {
                        vx = (vx > 0.f) ? vx : NEG_SLOPE * vx;
                        vy = (vy > 0.f) ? vy : NEG_SLOPE * vy;
                    }
                    *(__half2*)(orow + colbase + nf * 8) = __floats2half2_rn(vx, vy);
                }
            }
        }
    }
}

// ---------------------------------------------------------------------------
// Fused segment-mean pool + linear head: one block per graph (batch sorted).
// ---------------------------------------------------------------------------
__global__ void k_poolhead(const __half* __restrict__ h,
                           const float* __restrict__ hW, const float* __restrict__ hb,
                           float* __restrict__ out) {
    const int g = blockIdx.x;
    const int t = threadIdx.x;    // channel, 0..127
    const int s = g_gstart[g], e = g_gstart[g + 1];
    float acc = 0.f;
    for (int i = s; i < e; i++)
        acc += __half2float(h[(size_t)i * CH + t]);
    const float iv = 1.0f / (float)max(e - s, 1);
    const float p = acc * iv;
    __shared__ float r0[128], r1[128];
    r0[t] = p * hW[t * 2 + 0];
    r1[t] = p * hW[t * 2 + 1];
    __syncthreads();
    #pragma unroll
    for (int o = 64; o > 0; o >>= 1) {
        if (t < o) { r0[t] += r0[t + o]; r1[t] += r1[t + o]; }
        __syncthreads();
    }
    if (t == 0) {
        out[g * 2 + 0] = r0[0] + hb[0];
        out[g * 2 + 1] = r1[0] + hb[1];
    }
}

// ---------------------------------------------------------------------------
// Host launch
// ---------------------------------------------------------------------------
static void* sym_addr(const void* sym) {
    void* p = nullptr;
    cudaGetSymbolAddress(&p, sym);
    return p;
}

extern "C" void kernel_launch(void* const* d_in, const int* in_sizes, int n_in,
                              void* d_out, int out_size) {
    const float* x    = (const float*)d_in[0];
    const int*   ei   = (const int*)d_in[1];
    const int*   srcp = ei;
    const int*   dstp = ei + EE;
    const int*   batch = (const int*)d_in[2];
    const float* Wl0 = (const float*)d_in[3];
    const float* Wr0 = (const float*)d_in[4];
    const float* b0  = (const float*)d_in[5];
    const float* Wl  = (const float*)d_in[6];
    const float* Wr  = (const float*)d_in[7];
    const float* bb  = (const float*)d_in[8];
    const float* hW  = (const float*)d_in[9];
    const float* hb  = (const float*)d_in[10];
    float* out = (float*)d_out;

    __half* h16A  = (__half*)sym_addr(g_h16A);
    __half* h16B  = (__half*)sym_addr(g_h16B);
    __half* agg16 = (__half*)sym_addr(g_agg16);
    __half* x16   = (__half*)sym_addr(g_x16);
    __half* W16   = (__half*)sym_addr(g_W16);
    int*    deg   = (int*)sym_addr(g_deg);

    const int TPB = 256;

    // --- CSR build + fp16 conversions + graph bounds ---
    k_zero_i<<<(NN + TPB - 1) / TPB, TPB>>>(deg, NN);
    k_count<<<(EE + TPB - 1) / TPB, TPB>>>(dstp);
    k_prep<<<(NN * CIN + TPB - 1) / TPB, TPB>>>(x, Wl0, Wr0, Wl, Wr);
    k_gstart<<<3, 256>>>(batch);
    k_scan2<<<1, 1024>>>();
    k_fill<<<(EE + TPB - 1) / TPB, TPB>>>(srcp, dstp);

    const int aggBlocks = (NN * 32 + TPB - 1) / TPB;

    // --- conv 0 (C_IN=64 -> 128), ReLU ---
    k_agg16<64><<<aggBlocks, TPB>>>(x16, agg16);
    k_gemm16<64, 1><<<GEMM_BLOCKS, TPB>>>(agg16, x16, W16, b0, h16A);

    // --- convs 1..11 ---
    __half* hcur = h16A;
    __half* hnxt = h16B;
    for (int i = 0; i < 11; i++) {
        int ci = i + 1;
        k_agg16<128><<<aggBlocks, TPB>>>(hcur, agg16);
        const __half* wt = W16 + (size_t)(i + 1) * 128 * 256;
        const float* bi = bb + (size_t)i * CH;
        if (ci == 11) {
            k_gemm16<128, 0><<<GEMM_BLOCKS, TPB>>>(agg16, hcur, wt, bi, hnxt);
        } else if (ci == 3 || ci == 7) {
            k_gemm16<128, 2><<<GEMM_BLOCKS, TPB>>>(agg16, hcur, wt, bi, hnxt);
        } else {
            k_gemm16<128, 1><<<GEMM_BLOCKS, TPB>>>(agg16, hcur, wt, bi, hnxt);
        }
        __half* t = hcur; hcur = hnxt; hnxt = t;
    }

    // --- fused global mean pool + head ---
    k_poolhead<<<GG, 128>>>(hcur, hW, hb, out);
}